// round 3
// baseline (speedup 1.0000x reference)
#include <cuda_runtime.h>

// YOLO loss, fused single-kernel, high-occupancy version.
// pred [8192, 49*30] f32, target [8192, 49*25] f32 -> scalar f32.
// 3136 blocks x 128 threads, ONE 128-cell tile per block (max warps in
// flight to hide DRAM latency), last-block-done final reduction.

#define YS2       49
#define YB_P      30          // floats per cell (pred)
#define YB_T      25          // floats per cell (target)
#define CELLS     128         // cells per block (= threads)
#define NBLOCKS   3136        // 401408 / 128
#define NBATCH    8192.0

__device__ double       g_partials[NBLOCKS];
__device__ unsigned int g_ticket;          // zero-init; reset by last block

__global__ __launch_bounds__(CELLS) void yolo_loss_kernel(
    const float* __restrict__ pred, const float* __restrict__ tgt,
    float* __restrict__ out)
{
    __shared__ float  sp[CELLS * YB_P];    // 15360 B
    __shared__ float  st[CELLS * YB_T];    // 12800 B
    __shared__ float  wsum[CELLS / 32];
    __shared__ int    s_last;

    const int b   = blockIdx.x;
    const int tid = threadIdx.x;

    // ---- coalesced float4 staging: all loads issued before sync ----
    {
        const float4* gp = (const float4*)(pred + (size_t)b * CELLS * YB_P);
        const float4* gt = (const float4*)(tgt  + (size_t)b * CELLS * YB_T);
        float4* s4 = (float4*)sp;
        float4* t4 = (float4*)st;
        float4 rp[8], rt[7];
        #pragma unroll
        for (int k = 0; k < 7; k++) {           // 7*128 = 896 < 960
            rp[k] = gp[tid + k * CELLS];
            rt[k] = gt[tid + k * CELLS];
        }
        {   // pred remainder: 960 - 896 = 64 float4
            if (tid < 64) rp[7] = gp[tid + 7 * CELLS];
        }
        // target: 800 float4 total -> 6 full strides + 32 remainder
        // (rt[6] loaded above covers indices 768..895 but only 800 valid:
        //  guard it)
        #pragma unroll
        for (int k = 0; k < 6; k++) t4[tid + k * CELLS] = rt[k];
        if (tid + 6 * CELLS < CELLS * YB_T / 4) t4[tid + 6 * CELLS] = rt[6];
        #pragma unroll
        for (int k = 0; k < 7; k++) s4[tid + k * CELLS] = rp[k];
        if (tid < 64) s4[tid + 7 * CELLS] = rp[7];
    }
    __syncthreads();

    // ---- per-cell loss ----
    const float* pc = sp + tid * YB_P;
    const float* tc = st + tid * YB_T;

    const int cell = b * CELLS + tid;
    const int g    = cell % YS2;
    const float gy = (float)(g / 7);
    const float gx = (float)(g % 7);

    const float t0    = tc[0];
    const float objf  = (t0 == 1.0f) ? 1.0f : 0.0f;
    const float noobf = (t0 == 0.0f) ? 1.0f : 0.0f;

    const float tx = tc[1], ty = tc[2], tw = tc[3], th = tc[4];
    const float tcx = (gx + tx) / 7.0f;
    const float tcy = (gy + ty) / 7.0f;
    const float tx1 = tcx - tw * 0.5f, ty1 = tcy - th * 0.5f;
    const float tx2 = tcx + tw * 0.5f, ty2 = tcy + th * 0.5f;
    const float area_t = (tx2 - tx1) * (ty2 - ty1);

    float iou0, iou1;
    #pragma unroll
    for (int bb = 0; bb < 2; bb++) {
        const float px = fabsf(pc[bb * 5 + 1]);
        const float py = fabsf(pc[bb * 5 + 2]);
        const float pw = fabsf(pc[bb * 5 + 3]);
        const float ph = fabsf(pc[bb * 5 + 4]);
        const float cx = (gx + px) / 7.0f;
        const float cy = (gy + py) / 7.0f;
        const float x1 = cx - pw * 0.5f, y1 = cy - ph * 0.5f;
        const float x2 = cx + pw * 0.5f, y2 = cy + ph * 0.5f;
        const float ltx = fmaxf(x1, tx1), lty = fmaxf(y1, ty1);
        const float rbx = fminf(x2, tx2), rby = fminf(y2, ty2);
        const float iw  = fmaxf(rbx - ltx, 0.0f);
        const float ih  = fmaxf(rby - lty, 0.0f);
        const float inter  = iw * ih;
        const float area_p = (x2 - x1) * (y2 - y1);
        const float v = inter / (area_p + area_t - inter);
        if (bb == 0) iou0 = v; else iou1 = v;
    }

    const int   best    = (iou1 > iou0) ? 1 : 0;
    const float max_iou = best ? iou1 : iou0;
    const float* rbp = pc + best * 5;

    const float dx = rbp[1] - tx;
    const float dy = rbp[2] - ty;
    const float xy_loss = dx * dx + dy * dy;

    const float swd = sqrtf(fabsf(rbp[3])) - sqrtf(fabsf(tw));
    const float shd = sqrtf(fabsf(rbp[4])) - sqrtf(fabsf(th));
    const float wh_loss = swd * swd + shd * shd;

    const float doc = rbp[0] - max_iou;
    const float obj_conf = doc * doc;

    const float noobj_conf = 0.5f * (pc[0] * pc[0] + pc[5] * pc[5]);

    float cls = 0.0f;
    #pragma unroll
    for (int k = 0; k < 20; k++) {
        const float d = pc[10 + k] - tc[5 + k];
        cls += d * d;
    }

    float acc = objf * (5.0f * (xy_loss + wh_loss) + obj_conf + cls)
              + noobf * noobj_conf;

    // ---- deterministic block reduction ----
    #pragma unroll
    for (int o = 16; o > 0; o >>= 1)
        acc += __shfl_down_sync(0xffffffffu, acc, o);

    const int lane = tid & 31;
    const int wrp  = tid >> 5;
    if (lane == 0) wsum[wrp] = acc;
    __syncthreads();

    if (tid == 0) {
        double s = 0.0;
        #pragma unroll
        for (int w = 0; w < CELLS / 32; w++) s += (double)wsum[w];
        g_partials[b] = s;
        __threadfence();
        unsigned int ticket = atomicAdd(&g_ticket, 1u);
        s_last = (ticket == NBLOCKS - 1u) ? 1 : 0;
    }
    __syncthreads();

    // ---- last block: final reduction over all partials ----
    if (s_last) {
        __threadfence();
        __shared__ double dsum[CELLS / 32];

        double s = 0.0;
        for (int i = tid; i < NBLOCKS; i += CELLS)
            s += g_partials[i];

        #pragma unroll
        for (int o = 16; o > 0; o >>= 1)
            s += __shfl_down_sync(0xffffffffu, s, o);

        if (lane == 0) dsum[wrp] = s;
        __syncthreads();

        if (tid == 0) {
            double total = 0.0;
            #pragma unroll
            for (int w = 0; w < CELLS / 32; w++) total += dsum[w];
            out[0] = (float)(total / NBATCH);
            g_ticket = 0;   // reset for next graph replay
        }
    }
}

extern "C" void kernel_launch(void* const* d_in, const int* in_sizes, int n_in,
                              void* d_out, int out_size)
{
    const float* pred = (const float*)d_in[0];
    const float* tgt  = (const float*)d_in[1];
    float* out        = (float*)d_out;

    yolo_loss_kernel<<<NBLOCKS, CELLS>>>(pred, tgt, out);
}